// round 2
// baseline (speedup 1.0000x reference)
#include <cuda_runtime.h>

#define DINLINE __device__ __forceinline__

constexpr int B_ = 8, T_ = 64, N_ = 512, H_ = 128, E_ = 8192;
constexpr int S_ = B_ * N_;       // 4096 sequences
constexpr int G1_ = 128, G2_ = 64;
constexpr int MS = 16;            // sequences per LSTM block
constexpr int NT = 256;           // threads per LSTM block

// ---------------- device scratch (static globals; no allocation) -------------
__device__ float g_h[(size_t)S_ * T_ * H_];   // 128 MiB: layer activations, reused in place
__device__ float g_xl1[S_ * G1_];
__device__ float g_h1[S_ * G1_];
__device__ float g_xl2[S_ * G2_];
__device__ float g_h2[S_ * G2_];
__device__ float g_deg[N_];
__device__ float g_dis[N_];
__device__ int   g_is64;

// ---------------- activation helpers (exp-based, ~1e-6 err) ------------------
DINLINE float sigf(float x)  { return __fdividef(1.0f, 1.0f + __expf(-x)); }
DINLINE float tanh_(float x) { return __fdividef(2.0f, 1.0f + __expf(-2.0f * x)) - 1.0f; }

// ---------------- edge dtype detection + degree init -------------------------
__global__ void k_detect(const int* __restrict__ ei32) {
    __shared__ int nz;
    int tid = threadIdx.x;
    if (tid == 0) nz = 0;
    if (tid < N_) g_deg[tid] = 1.0f;   // self-loop
    __syncthreads();
    int acc = 0;
    // If data is int64, the high 32-bit word of every value (0 <= v < 512) is 0.
    // If data is int32, odd int32 slots hold real indices (statistically nonzero).
    for (int i = 1 + 2 * tid; i < 2 * E_; i += 2 * blockDim.x) acc |= ei32[i];
    if (acc) atomicOr(&nz, 1);
    __syncthreads();
    if (tid == 0) g_is64 = (nz == 0) ? 1 : 0;
}

DINLINE int edge_at(const void* p, int is64, int idx) {
    return is64 ? (int)((const long long*)p)[idx] : ((const int*)p)[idx];
}

__global__ void k_deg(const void* __restrict__ ei) {
    int e = blockIdx.x * blockDim.x + threadIdx.x;
    if (e < E_) {
        int dst = edge_at(ei, g_is64, E_ + e);
        atomicAdd(&g_deg[dst], 1.0f);
    }
}

__global__ void k_dis() {
    int n = blockIdx.x * blockDim.x + threadIdx.x;
    if (n < N_) g_dis[n] = rsqrtf(g_deg[n]);
}

// ---------------- LSTM layer kernel ------------------------------------------
// MODE 0: input = x [B,T,N] scalar per (s,t), W_ih is [512,1]
// MODE 1: input = g_h (prev layer output) [S,T,H], W_ih is [512,128]
// Output always written to g_h (in-place is safe: [s][t] row is staged to SMEM
// and synced before it is overwritten).
template <int MODE>
__global__ void __launch_bounds__(NT, 2) lstm_kernel(
    const float* __restrict__ x,
    const float* __restrict__ w_ih,
    const float* __restrict__ w_hh,
    const float* __restrict__ b_ih,
    const float* __restrict__ b_hh)
{
    __shared__ float h_sh[2][MS][H_];
    __shared__ float x_sh[2][MS][H_];

    const int tid  = threadIdx.x;
    const int j    = tid & (H_ - 1);   // hidden unit
    const int grp  = tid >> 7;         // 0..1
    const int mbase = grp * 8;
    const int s0   = blockIdx.x * MS;

    float bsum[4], w0[4];
#pragma unroll
    for (int g = 0; g < 4; g++) {
        int r = g * H_ + j;
        bsum[g] = b_ih[r] + b_hh[r];
        if (MODE == 0) w0[g] = w_ih[r];
    }
    const float* wh = w_hh + j * H_;                         // gate g at +g*H_*H_
    const float* wi = (MODE == 1) ? (w_ih + j * H_) : w_ih;

    float c[8];
#pragma unroll
    for (int mm = 0; mm < 8; mm++) c[mm] = 0.0f;
    for (int i = tid; i < MS * H_; i += NT) ((float*)h_sh[0])[i] = 0.0f;
    __syncthreads();

    for (int t = 0; t < T_; t++) {
        const int rb = t & 1, wb = rb ^ 1;
        // --- stage this step's layer input ---
        if (MODE == 0) {
            if (tid < MS) {
                int s = s0 + tid;
                x_sh[rb][tid][0] = x[(s >> 9) * (T_ * N_) + t * N_ + (s & (N_ - 1))];
            }
        } else {
            for (int i = tid; i < MS * H_; i += NT) {
                int m = i >> 7, k = i & (H_ - 1);
                x_sh[rb][m][k] = g_h[((size_t)(s0 + m) * T_ + t) * H_ + k];
            }
        }
        __syncthreads();

        float acc[8][4];
#pragma unroll
        for (int mm = 0; mm < 8; mm++)
#pragma unroll
            for (int g = 0; g < 4; g++) acc[mm][g] = bsum[g];

        if (MODE == 0) {
#pragma unroll
            for (int mm = 0; mm < 8; mm++) {
                float xv = x_sh[rb][mbase + mm][0];
#pragma unroll
                for (int g = 0; g < 4; g++) acc[mm][g] = fmaf(xv, w0[g], acc[mm][g]);
            }
        }

#pragma unroll 2
        for (int k = 0; k < H_; k += 2) {
            float2 whv[4];
#pragma unroll
            for (int g = 0; g < 4; g++)
                whv[g] = *(const float2*)(wh + g * (H_ * H_) + k);
#pragma unroll
            for (int mm = 0; mm < 8; mm++) {
                float2 hv = *(const float2*)&h_sh[rb][mbase + mm][k];
#pragma unroll
                for (int g = 0; g < 4; g++) {
                    acc[mm][g] = fmaf(hv.x, whv[g].x, acc[mm][g]);
                    acc[mm][g] = fmaf(hv.y, whv[g].y, acc[mm][g]);
                }
            }
            if (MODE == 1) {
                float2 wiv[4];
#pragma unroll
                for (int g = 0; g < 4; g++)
                    wiv[g] = *(const float2*)(wi + g * (H_ * H_) + k);
#pragma unroll
                for (int mm = 0; mm < 8; mm++) {
                    float2 xv = *(const float2*)&x_sh[rb][mbase + mm][k];
#pragma unroll
                    for (int g = 0; g < 4; g++) {
                        acc[mm][g] = fmaf(xv.x, wiv[g].x, acc[mm][g]);
                        acc[mm][g] = fmaf(xv.y, wiv[g].y, acc[mm][g]);
                    }
                }
            }
        }

#pragma unroll
        for (int mm = 0; mm < 8; mm++) {
            float ig = sigf(acc[mm][0]);
            float fg = sigf(acc[mm][1]);
            float gg = tanh_(acc[mm][2]);
            float og = sigf(acc[mm][3]);
            float cn = fg * c[mm] + ig * gg;
            c[mm] = cn;
            float hn = og * tanh_(cn);
            int m = mbase + mm;
            h_sh[wb][m][j] = hn;
            g_h[((size_t)(s0 + m) * T_ + t) * H_ + j] = hn;
        }
        // single top-of-loop sync per step suffices (double-buffered h/x)
    }
}

// ---------------- GCN ---------------------------------------------------------
// xl1[row][g] = feats[row] . gcn1_w[g]   (row = b*N+n, feats = g_h at t=T-1)
__global__ void k_lin1(const float* __restrict__ w) {
    __shared__ float fr[H_];
    int row = blockIdx.x, tid = threadIdx.x;   // 128 threads
    fr[tid] = g_h[((size_t)row * T_ + (T_ - 1)) * H_ + tid];
    __syncthreads();
    const float* wr = w + tid * H_;
    float a = 0.0f;
#pragma unroll 4
    for (int k = 0; k < H_; k++) a = fmaf(fr[k], wr[k], a);
    g_xl1[row * G1_ + tid] = a;
}

// xl2[row][g] = relu(h1[row]) . gcn2_w[g]
__global__ void k_lin2(const float* __restrict__ w) {
    __shared__ float fr[G1_];
    int row = blockIdx.x, tid = threadIdx.x;   // 64 threads
    fr[tid]      = fmaxf(g_h1[row * G1_ + tid], 0.0f);
    fr[tid + 64] = fmaxf(g_h1[row * G1_ + tid + 64], 0.0f);
    __syncthreads();
    const float* wr = w + tid * G1_;
    float a = 0.0f;
#pragma unroll 4
    for (int k = 0; k < G1_; k++) a = fmaf(fr[k], wr[k], a);
    g_xl2[row * G2_ + tid] = a;
}

// out = bias + self-loop contribution (dis[n]^2 * xl)
template <int Gd>
__global__ void k_agg_init(const float* __restrict__ bias) {
    const float* xl = (Gd == G1_) ? g_xl1 : g_xl2;
    float* outb     = (Gd == G1_) ? g_h1  : g_h2;
    int i = blockIdx.x * blockDim.x + threadIdx.x;
    if (i < S_ * Gd) {
        int g = i % Gd;
        int n = (i / Gd) & (N_ - 1);
        float d = g_dis[n];
        outb[i] = bias[g] + xl[i] * d * d;
    }
}

// scatter-add edge messages
template <int Gd>
__global__ void k_agg_edge(const void* __restrict__ ei) {
    const float* xl = (Gd == G1_) ? g_xl1 : g_xl2;
    float* outb     = (Gd == G1_) ? g_h1  : g_h2;
    int i = blockIdx.x * blockDim.x + threadIdx.x;
    constexpr int per = B_ * Gd;
    if (i >= E_ * per) return;
    int e = i / per;
    int r = i - e * per;
    int b = r / Gd;
    int g = r - b * Gd;
    int is64 = g_is64;
    int src = edge_at(ei, is64, e);
    int dst = edge_at(ei, is64, E_ + e);
    float norm = g_dis[src] * g_dis[dst];
    atomicAdd(&outb[(b * N_ + dst) * Gd + g],
              xl[(b * N_ + src) * Gd + g] * norm);
}

// mean pool over nodes + linear classifier
__global__ void k_final(const float* __restrict__ cls_w,
                        const float* __restrict__ cls_b,
                        float* __restrict__ out) {
    int b = blockIdx.x, tid = threadIdx.x;   // 256 threads
    __shared__ float red[256];
    float a = 0.0f;
    for (int i = tid; i < N_ * G2_; i += 256) {
        int g = i & (G2_ - 1);
        a = fmaf(fmaxf(g_h2[b * (N_ * G2_) + i], 0.0f), cls_w[g], a);
    }
    red[tid] = a;
    __syncthreads();
    for (int s = 128; s > 0; s >>= 1) {
        if (tid < s) red[tid] += red[tid + s];
        __syncthreads();
    }
    if (tid == 0) out[b] = red[0] * (1.0f / N_) + cls_b[0];
}

// ---------------- launch ------------------------------------------------------
extern "C" void kernel_launch(void* const* d_in, const int* in_sizes, int n_in,
                              void* d_out, int out_size) {
    const float* x      = (const float*)d_in[0];
    const void*  ei     = d_in[1];
    const float* w_ih0  = (const float*)d_in[2];
    const float* w_hh0  = (const float*)d_in[3];
    const float* b_ih0  = (const float*)d_in[4];
    const float* b_hh0  = (const float*)d_in[5];
    const float* w_ih1  = (const float*)d_in[6];
    const float* w_hh1  = (const float*)d_in[7];
    const float* b_ih1  = (const float*)d_in[8];
    const float* b_hh1  = (const float*)d_in[9];
    const float* w_ih2  = (const float*)d_in[10];
    const float* w_hh2  = (const float*)d_in[11];
    const float* b_ih2  = (const float*)d_in[12];
    const float* b_hh2  = (const float*)d_in[13];
    const float* gcn1_w = (const float*)d_in[14];
    const float* gcn1_b = (const float*)d_in[15];
    const float* gcn2_w = (const float*)d_in[16];
    const float* gcn2_b = (const float*)d_in[17];
    const float* cls_w  = (const float*)d_in[18];
    const float* cls_b  = (const float*)d_in[19];
    float* out = (float*)d_out;

    k_detect<<<1, 512>>>((const int*)ei);

    lstm_kernel<0><<<S_ / MS, NT>>>(x, w_ih0, w_hh0, b_ih0, b_hh0);
    lstm_kernel<1><<<S_ / MS, NT>>>(x, w_ih1, w_hh1, b_ih1, b_hh1);
    lstm_kernel<1><<<S_ / MS, NT>>>(x, w_ih2, w_hh2, b_ih2, b_hh2);

    k_deg<<<(E_ + 255) / 256, 256>>>(ei);
    k_dis<<<2, 256>>>();

    k_lin1<<<S_, 128>>>(gcn1_w);
    k_agg_init<G1_><<<(S_ * G1_ + 255) / 256, 256>>>(gcn1_b);
    k_agg_edge<G1_><<<(E_ * B_ * G1_ + 255) / 256, 256>>>(ei);

    k_lin2<<<S_, 64>>>(gcn2_w);
    k_agg_init<G2_><<<(S_ * G2_ + 255) / 256, 256>>>(gcn2_b);
    k_agg_edge<G2_><<<(E_ * B_ * G2_ + 255) / 256, 256>>>(ei);

    k_final<<<B_, 256>>>(cls_w, cls_b, out);
}

// round 3
// speedup vs baseline: 4.2666x; 4.2666x over previous
#include <cuda_runtime.h>

#define DINLINE __device__ __forceinline__

constexpr int B_ = 8, T_ = 64, N_ = 512, H_ = 128, E_ = 8192;
constexpr int S_ = B_ * N_;       // 4096 sequences
constexpr int G1_ = 128, G2_ = 64;
constexpr int MS = 16;            // sequences per LSTM block
constexpr int NT = 256;           // threads per LSTM block
constexpr int G4H = 4 * H_;       // 512 gate rows

// ---------------- device scratch (static globals; no allocation) -------------
__device__ float g_h[(size_t)S_ * T_ * H_];            // 128 MiB activations
__device__ float g_xp[(size_t)S_ * T_ * G4H];          // 512 MiB input projections
__device__ float g_wtA[H_ * G4H];                      // transposed w_ih (layer 1/2)
__device__ float g_wtB[H_ * G4H];                      // transposed w_hh
__device__ float g_xl1[S_ * G1_];
__device__ float g_h1[S_ * G1_];
__device__ float g_xl2[S_ * G2_];
__device__ float g_h2[S_ * G2_];
__device__ float g_deg[N_];
__device__ float g_dis[N_];
__device__ int   g_is64;

// ---------------- activation helpers (exp-based, ~1e-6 err) ------------------
DINLINE float sigf(float x)  { return __fdividef(1.0f, 1.0f + __expf(-x)); }
DINLINE float tanh_(float x) { return __fdividef(2.0f, 1.0f + __expf(-2.0f * x)) - 1.0f; }

// ---------------- edge dtype detection + degree init -------------------------
__global__ void k_detect(const int* __restrict__ ei32) {
    __shared__ int nz;
    int tid = threadIdx.x;
    if (tid == 0) nz = 0;
    if (tid < N_) g_deg[tid] = 1.0f;   // self-loop
    __syncthreads();
    int acc = 0;
    for (int i = 1 + 2 * tid; i < 2 * E_; i += 2 * blockDim.x) acc |= ei32[i];
    if (acc) atomicOr(&nz, 1);
    __syncthreads();
    if (tid == 0) g_is64 = (nz == 0) ? 1 : 0;
}

DINLINE int edge_at(const void* p, int is64, int idx) {
    return is64 ? (int)((const long long*)p)[idx] : ((const int*)p)[idx];
}

__global__ void k_deg(const void* __restrict__ ei) {
    int e = blockIdx.x * blockDim.x + threadIdx.x;
    if (e < E_) atomicAdd(&g_deg[edge_at(ei, g_is64, E_ + e)], 1.0f);
}

__global__ void k_dis() {
    int n = blockIdx.x * blockDim.x + threadIdx.x;
    if (n < N_) g_dis[n] = rsqrtf(g_deg[n]);
}

// ---------------- weight transpose: w[4H][H] -> wt[H][4H] ---------------------
__global__ void k_transpose(const float* __restrict__ w, float* __restrict__ wt) {
    int i = blockIdx.x * blockDim.x + threadIdx.x;   // 65536
    int k = i >> 9, r = i & (G4H - 1);
    wt[i] = w[r * H_ + k];
}

// ---------------- input-projection GEMM: xp = h_prev @ W_ih^T + b ------------
// rows r = s*T + t, 16 rows per block, 256 threads.
__global__ void __launch_bounds__(256, 2) proj_kernel(
    const float* __restrict__ wt,     // [H][4H] transposed
    const float* __restrict__ b_ih,
    const float* __restrict__ b_hh)
{
    __shared__ float xs[16][H_];
    const int tid = threadIdx.x;
    const int j = tid & (H_ - 1);
    const int mbase = (tid >> 7) * 8;
    const size_t r0 = (size_t)blockIdx.x * 16;

    {   // stage 16 rows of g_h (contiguous) via float4
        const float4* src = (const float4*)(g_h + r0 * H_);
        float4* dst = (float4*)xs;
        for (int i = tid; i < 16 * H_ / 4; i += 256) dst[i] = src[i];
    }
    __syncthreads();

    float dot[8][4];
#pragma unroll
    for (int g = 0; g < 4; g++) {
        float b = b_ih[g * H_ + j] + b_hh[g * H_ + j];
#pragma unroll
        for (int mm = 0; mm < 8; mm++) dot[mm][g] = b;
    }

#pragma unroll 4
    for (int k0 = 0; k0 < H_; k0 += 4) {
        float4 hv[8];
#pragma unroll
        for (int mm = 0; mm < 8; mm++) hv[mm] = *(const float4*)&xs[mbase + mm][k0];
#pragma unroll
        for (int kk = 0; kk < 4; kk++) {
            float wv[4];
#pragma unroll
            for (int g = 0; g < 4; g++) wv[g] = wt[(k0 + kk) * G4H + g * H_ + j];
#pragma unroll
            for (int mm = 0; mm < 8; mm++) {
                float hk = (kk == 0) ? hv[mm].x : (kk == 1) ? hv[mm].y
                         : (kk == 2) ? hv[mm].z : hv[mm].w;
#pragma unroll
                for (int g = 0; g < 4; g++) dot[mm][g] = fmaf(hk, wv[g], dot[mm][g]);
            }
        }
    }

#pragma unroll
    for (int mm = 0; mm < 8; mm++)
#pragma unroll
        for (int g = 0; g < 4; g++)
            g_xp[(r0 + mbase + mm) * G4H + g * H_ + j] = dot[mm][g];
}

// ---------------- recurrent LSTM kernel ---------------------------------------
// MODE 0: layer 0 (scalar input, w_ih [512][1], biases applied here)
// MODE 1: xp precomputed (includes biases)
template <int MODE, int WRITE_ALL>
__global__ void __launch_bounds__(NT, 2) lstm_rec(
    const float* __restrict__ x,       // MODE 0 only
    const float* __restrict__ w_ih,    // MODE 0 only [512]
    const float* __restrict__ wt_hh,   // [H][4H] transposed
    const float* __restrict__ b_ih,
    const float* __restrict__ b_hh)
{
    __shared__ float h_sh[2][MS][H_];
    __shared__ float x_sh[2][MS];

    const int tid = threadIdx.x;
    const int j = tid & (H_ - 1);
    const int mbase = (tid >> 7) * 8;
    const int s0 = blockIdx.x * MS;

    float bsum[4], w0[4];
    if (MODE == 0) {
#pragma unroll
        for (int g = 0; g < 4; g++) {
            bsum[g] = b_ih[g * H_ + j] + b_hh[g * H_ + j];
            w0[g]   = w_ih[g * H_ + j];
        }
    }

    float c[8];
#pragma unroll
    for (int mm = 0; mm < 8; mm++) c[mm] = 0.0f;
    for (int i = tid; i < MS * H_; i += NT) ((float*)h_sh[0])[i] = 0.0f;
    if (MODE == 0 && tid < MS) {
        int s = s0 + tid;
        x_sh[0][tid] = x[(s >> 9) * (T_ * N_) + 0 * N_ + (s & (N_ - 1))];
    }
    __syncthreads();

    for (int t = 0; t < T_; t++) {
        const int rb = t & 1, wb = rb ^ 1;

        // issue xp loads early (DRAM latency hides under the GEMM below)
        float xpr[8][4];
        if (MODE == 1) {
#pragma unroll
            for (int mm = 0; mm < 8; mm++) {
                const float* p = g_xp + ((size_t)(s0 + mbase + mm) * T_ + t) * G4H + j;
#pragma unroll
                for (int g = 0; g < 4; g++) xpr[mm][g] = p[g * H_];
            }
        } else {
            // stage next step's scalar input
            if (t + 1 < T_ && tid < MS) {
                int s = s0 + tid;
                x_sh[wb][tid] = x[(s >> 9) * (T_ * N_) + (t + 1) * N_ + (s & (N_ - 1))];
            }
        }

        float dot[8][4];
#pragma unroll
        for (int mm = 0; mm < 8; mm++)
#pragma unroll
            for (int g = 0; g < 4; g++) dot[mm][g] = 0.0f;

#pragma unroll 4
        for (int k0 = 0; k0 < H_; k0 += 4) {
            float4 hv[8];
#pragma unroll
            for (int mm = 0; mm < 8; mm++)
                hv[mm] = *(const float4*)&h_sh[rb][mbase + mm][k0];
#pragma unroll
            for (int kk = 0; kk < 4; kk++) {
                float wv[4];
#pragma unroll
                for (int g = 0; g < 4; g++)
                    wv[g] = wt_hh[(k0 + kk) * G4H + g * H_ + j];
#pragma unroll
                for (int mm = 0; mm < 8; mm++) {
                    float hk = (kk == 0) ? hv[mm].x : (kk == 1) ? hv[mm].y
                             : (kk == 2) ? hv[mm].z : hv[mm].w;
#pragma unroll
                    for (int g = 0; g < 4; g++)
                        dot[mm][g] = fmaf(hk, wv[g], dot[mm][g]);
                }
            }
        }

#pragma unroll
        for (int mm = 0; mm < 8; mm++) {
            float ga[4];
            if (MODE == 1) {
#pragma unroll
                for (int g = 0; g < 4; g++) ga[g] = dot[mm][g] + xpr[mm][g];
            } else {
                float xv = x_sh[rb][mbase + mm];
#pragma unroll
                for (int g = 0; g < 4; g++) ga[g] = fmaf(xv, w0[g], dot[mm][g] + bsum[g]);
            }
            float ig = sigf(ga[0]);
            float fg = sigf(ga[1]);
            float gg = tanh_(ga[2]);
            float og = sigf(ga[3]);
            float cn = fg * c[mm] + ig * gg;
            c[mm] = cn;
            float hn = og * tanh_(cn);
            h_sh[wb][mbase + mm][j] = hn;
            if (WRITE_ALL || t == T_ - 1)
                g_h[((size_t)(s0 + mbase + mm) * T_ + t) * H_ + j] = hn;
        }
        __syncthreads();
    }
}

// ---------------- GCN ---------------------------------------------------------
__global__ void k_lin1(const float* __restrict__ w) {
    __shared__ float fr[H_];
    int row = blockIdx.x, tid = threadIdx.x;   // 128 threads
    fr[tid] = g_h[((size_t)row * T_ + (T_ - 1)) * H_ + tid];
    __syncthreads();
    const float* wr = w + tid * H_;
    float a = 0.0f;
#pragma unroll 4
    for (int k = 0; k < H_; k++) a = fmaf(fr[k], wr[k], a);
    g_xl1[row * G1_ + tid] = a;
}

__global__ void k_lin2(const float* __restrict__ w) {
    __shared__ float fr[G1_];
    int row = blockIdx.x, tid = threadIdx.x;   // 64 threads
    fr[tid]      = fmaxf(g_h1[row * G1_ + tid], 0.0f);
    fr[tid + 64] = fmaxf(g_h1[row * G1_ + tid + 64], 0.0f);
    __syncthreads();
    const float* wr = w + tid * G1_;
    float a = 0.0f;
#pragma unroll 4
    for (int k = 0; k < G1_; k++) a = fmaf(fr[k], wr[k], a);
    g_xl2[row * G2_ + tid] = a;
}

template <int Gd>
__global__ void k_agg_init(const float* __restrict__ bias) {
    const float* xl = (Gd == G1_) ? g_xl1 : g_xl2;
    float* outb     = (Gd == G1_) ? g_h1  : g_h2;
    int i = blockIdx.x * blockDim.x + threadIdx.x;
    if (i < S_ * Gd) {
        int g = i % Gd;
        int n = (i / Gd) & (N_ - 1);
        float d = g_dis[n];
        outb[i] = bias[g] + xl[i] * d * d;
    }
}

template <int Gd>
__global__ void k_agg_edge(const void* __restrict__ ei) {
    const float* xl = (Gd == G1_) ? g_xl1 : g_xl2;
    float* outb     = (Gd == G1_) ? g_h1  : g_h2;
    int i = blockIdx.x * blockDim.x + threadIdx.x;
    constexpr int per = B_ * Gd;
    if (i >= E_ * per) return;
    int e = i / per;
    int r = i - e * per;
    int b = r / Gd;
    int g = r - b * Gd;
    int is64 = g_is64;
    int src = edge_at(ei, is64, e);
    int dst = edge_at(ei, is64, E_ + e);
    float norm = g_dis[src] * g_dis[dst];
    atomicAdd(&outb[(b * N_ + dst) * Gd + g],
              xl[(b * N_ + src) * Gd + g] * norm);
}

__global__ void k_final(const float* __restrict__ cls_w,
                        const float* __restrict__ cls_b,
                        float* __restrict__ out) {
    int b = blockIdx.x, tid = threadIdx.x;   // 256 threads
    __shared__ float red[256];
    float a = 0.0f;
    for (int i = tid; i < N_ * G2_; i += 256) {
        int g = i & (G2_ - 1);
        a = fmaf(fmaxf(g_h2[b * (N_ * G2_) + i], 0.0f), cls_w[g], a);
    }
    red[tid] = a;
    __syncthreads();
    for (int s = 128; s > 0; s >>= 1) {
        if (tid < s) red[tid] += red[tid + s];
        __syncthreads();
    }
    if (tid == 0) out[b] = red[0] * (1.0f / N_) + cls_b[0];
}

// ---------------- launch ------------------------------------------------------
extern "C" void kernel_launch(void* const* d_in, const int* in_sizes, int n_in,
                              void* d_out, int out_size) {
    const float* x      = (const float*)d_in[0];
    const void*  ei     = d_in[1];
    const float* w_ih0  = (const float*)d_in[2];
    const float* w_hh0  = (const float*)d_in[3];
    const float* b_ih0  = (const float*)d_in[4];
    const float* b_hh0  = (const float*)d_in[5];
    const float* w_ih1  = (const float*)d_in[6];
    const float* w_hh1  = (const float*)d_in[7];
    const float* b_ih1  = (const float*)d_in[8];
    const float* b_hh1  = (const float*)d_in[9];
    const float* w_ih2  = (const float*)d_in[10];
    const float* w_hh2  = (const float*)d_in[11];
    const float* b_ih2  = (const float*)d_in[12];
    const float* b_hh2  = (const float*)d_in[13];
    const float* gcn1_w = (const float*)d_in[14];
    const float* gcn1_b = (const float*)d_in[15];
    const float* gcn2_w = (const float*)d_in[16];
    const float* gcn2_b = (const float*)d_in[17];
    const float* cls_w  = (const float*)d_in[18];
    const float* cls_b  = (const float*)d_in[19];
    float* out = (float*)d_out;

    float* wtA; cudaGetSymbolAddress((void**)&wtA, g_wtA);
    float* wtB; cudaGetSymbolAddress((void**)&wtB, g_wtB);

    k_detect<<<1, 512>>>((const int*)ei);

    const int TB = (H_ * G4H + 255) / 256;
    const int PB = (S_ * T_) / 16;

    // ---- layer 0 ----
    k_transpose<<<TB, 256>>>(w_hh0, wtB);
    lstm_rec<0, 1><<<S_ / MS, NT>>>(x, w_ih0, wtB, b_ih0, b_hh0);

    // ---- layer 1 ----
    k_transpose<<<TB, 256>>>(w_ih1, wtA);
    proj_kernel<<<PB, 256>>>(wtA, b_ih1, b_hh1);
    k_transpose<<<TB, 256>>>(w_hh1, wtB);
    lstm_rec<1, 1><<<S_ / MS, NT>>>(nullptr, nullptr, wtB, nullptr, nullptr);

    // ---- layer 2 ----
    k_transpose<<<TB, 256>>>(w_ih2, wtA);
    proj_kernel<<<PB, 256>>>(wtA, b_ih2, b_hh2);
    k_transpose<<<TB, 256>>>(w_hh2, wtB);
    lstm_rec<1, 0><<<S_ / MS, NT>>>(nullptr, nullptr, wtB, nullptr, nullptr);

    // ---- GCN ----
    k_deg<<<(E_ + 255) / 256, 256>>>(ei);
    k_dis<<<2, 256>>>();

    k_lin1<<<S_, 128>>>(gcn1_w);
    k_agg_init<G1_><<<(S_ * G1_ + 255) / 256, 256>>>(gcn1_b);
    k_agg_edge<G1_><<<(E_ * B_ * G1_ + 255) / 256, 256>>>(ei);

    k_lin2<<<S_, 64>>>(gcn2_w);
    k_agg_init<G2_><<<(S_ * G2_ + 255) / 256, 256>>>(gcn2_b);
    k_agg_edge<G2_><<<(E_ * B_ * G2_ + 255) / 256, 256>>>(ei);

    k_final<<<B_, 256>>>(cls_w, cls_b, out);
}